// round 1
// baseline (speedup 1.0000x reference)
#include <cuda_runtime.h>

#define KS 93          // gaussian kernel size (static, matches reference)
#define NPTS 256       // points per batch
#define W_OUT 512
#define H_OUT 512

// Normalized separable 1-D gaussian weights: gnorm[i] = g[i] / sum(g),
// so patch value k[dr][dc] = gnorm[dr] * gnorm[dc]  (== g_dr*g_dc/(Σg)^2).
__device__ float d_gnorm[KS];

__global__ void gauss_setup_kernel(const float* __restrict__ sigma_ptr) {
    __shared__ float g[KS];
    __shared__ float ssum;
    const int i = threadIdx.x;
    const float s = fabsf(sigma_ptr[0]);
    const float inv2s2 = 1.0f / (2.0f * s * s);
    if (i < KS) {
        float a = (float)(i - KS / 2);            // ax in [-46, 46]
        g[i] = expf(-(a * a) * inv2s2);
    }
    __syncthreads();
    if (i == 0) {
        float t = 0.0f;
        #pragma unroll
        for (int k = 0; k < KS; k++) t += g[k];
        ssum = t;
    }
    __syncthreads();
    if (i < KS) d_gnorm[i] = g[i] / ssum;
}

// One block per (batch, output row). 128 threads; each thread owns 4 columns
// (t, t+128, t+256, t+384). Patch width 93 < 128, so at most one of a thread's
// columns is covered by any given point.
__global__ __launch_bounds__(128)
void density_kernel(const float* __restrict__ labels, float* __restrict__ out) {
    const int b   = blockIdx.x >> 9;     // / 512
    const int row = blockIdx.x & 511;
    const int t   = threadIdx.x;

    __shared__ float gn[KS];
    __shared__ int   sC0[NPTS];
    __shared__ float sW[NPTS];

    if (t < KS) gn[t] = d_gnorm[t];
    __syncthreads();

    // Phase 1: classify all 256 points of this batch against this row.
    // starts(out-coords) = trunc(label - 46.5); active iff 0 <= row-R0 < 93.
    const float* lab = labels + (size_t)b * NPTS * 2;
    #pragma unroll
    for (int k = 0; k < 2; k++) {
        const int n = t + k * 128;
        const float l0 = lab[2 * n + 0];          // height coord -> rows
        const float l1 = lab[2 * n + 1];          // width  coord -> cols
        const int R0 = (int)truncf(l0 - 46.5f);
        const int dr = row - R0;
        if ((unsigned)dr < (unsigned)KS) {
            sC0[n] = (int)truncf(l1 - 46.5f);
            sW[n]  = gn[dr];                      // strictly > 0 when active
        } else {
            sW[n]  = 0.0f;                        // sentinel: inactive
        }
    }
    __syncthreads();

    // Phase 2: accumulate over active points. Coherent branch (w is uniform
    // across the block for a given n), deterministic summation order.
    float a0 = 0.f, a1 = 0.f, a2 = 0.f, a3 = 0.f;
    for (int n = 0; n < NPTS; n++) {
        const float w = sW[n];
        if (w == 0.0f) continue;
        const int c0 = sC0[n];
        const int d0 = t - c0;                    // conflict-free gn[] access
        if ((unsigned)d0 < (unsigned)KS)         a0 = fmaf(w, gn[d0], a0);
        const int d1 = d0 + 128;
        if ((unsigned)d1 < (unsigned)KS)         a1 = fmaf(w, gn[d1], a1);
        const int d2 = d0 + 256;
        if ((unsigned)d2 < (unsigned)KS)         a2 = fmaf(w, gn[d2], a2);
        const int d3 = d0 + 384;
        if ((unsigned)d3 < (unsigned)KS)         a3 = fmaf(w, gn[d3], a3);
    }

    // Coalesced row write; every output element is written exactly once.
    float* o = out + (size_t)blockIdx.x * W_OUT;
    o[t]       = a0;
    o[t + 128] = a1;
    o[t + 256] = a2;
    o[t + 384] = a3;
}

extern "C" void kernel_launch(void* const* d_in, const int* in_sizes, int n_in,
                              void* d_out, int out_size) {
    // metadata order: [0] batch_images (unused by the math),
    //                 [1] batch_labels [8,256,2] f32, [2] sigma scalar f32
    const float* labels = (const float*)d_in[1];
    const float* sigma  = (const float*)d_in[2];
    float* out = (float*)d_out;                   // [8,1,512,512] f32

    gauss_setup_kernel<<<1, 128>>>(sigma);
    density_kernel<<<8 * H_OUT, 128>>>(labels, out);
}

// round 3
// speedup vs baseline: 2.8414x; 2.8414x over previous
#include <cuda_runtime.h>

#define KS 93          // gaussian kernel size (static, matches reference)
#define NPTS 256       // points per batch
#define W_OUT 512
#define H_OUT 512
#define RPB 8          // rows per block
#define NT 128         // threads per block

// Normalized separable 1-D gaussian weights: gnorm[i] = g[i] / sum(g),
// so patch value k[dr][dc] = gnorm[dr] * gnorm[dc].
__device__ float d_gnorm[KS];

__global__ void gauss_setup_kernel(const float* __restrict__ sigma_ptr) {
    __shared__ float g[KS];
    __shared__ float ssum;
    const int i = threadIdx.x;
    const float s = fabsf(sigma_ptr[0]);
    const float inv2s2 = 1.0f / (2.0f * s * s);
    if (i < KS) {
        float a = (float)(i - KS / 2);            // ax in [-46, 46]
        g[i] = expf(-(a * a) * inv2s2);
    }
    __syncthreads();
    if (i == 0) {
        float t = 0.0f;
        #pragma unroll
        for (int k = 0; k < KS; k++) t += g[k];
        ssum = t;
    }
    __syncthreads();
    if (i < KS) d_gnorm[i] = g[i] / ssum;
}

// One block per (batch, 8-row group). 128 threads; thread t owns columns
// t, t+128, t+256, t+384 for all 8 rows (32 accumulators).
// Phase 1: classify all 256 points once per row-group, ballot-compact the
// active ones (deterministic order), precompute their 8 row weights.
// Phase 2: loop over only the ~50 active points.
__global__ __launch_bounds__(NT)
void density_kernel(const float* __restrict__ labels, float* __restrict__ out) {
    const int b       = blockIdx.x >> 6;          // 64 row-groups per batch
    const int rowBase = (blockIdx.x & 63) * RPB;
    const int t    = threadIdx.x;
    const int warp = t >> 5;
    const int lane = t & 31;

    // 16B-aligned first so float4 loads from sW are legal.
    __shared__ __align__(16) float sW[NPTS][RPB]; // 8 row-weights per point
    __shared__ float gn[KS];
    __shared__ int   sC0[NPTS];
    __shared__ int   warpCnt[8];                  // 4 warps x 2 passes

    if (t < KS) gn[t] = d_gnorm[t];
    __syncthreads();

    // ---- Phase 1: classify + compact -------------------------------------
    const float* lab = labels + (size_t)b * NPTS * 2;
    // point indices: pass0 -> n = t, pass1 -> n = t + 128
    const float l0a = lab[2 * t + 0];
    const float l1a = lab[2 * t + 1];
    const float l0b = lab[2 * (t + NT) + 0];
    const float l1b = lab[2 * (t + NT) + 1];
    const int R0a = (int)truncf(l0a - 46.5f);
    const int R0b = (int)truncf(l0b - 46.5f);
    const int da = rowBase - R0a;   // active iff exists r in [0,8): da+r in [0,93)
    const int db = rowBase - R0b;   //   <=> da in [-7, 92]
    const bool actA = (unsigned)(da + RPB - 1) < (unsigned)(KS + RPB - 1);
    const bool actB = (unsigned)(db + RPB - 1) < (unsigned)(KS + RPB - 1);
    const unsigned balA = __ballot_sync(0xffffffffu, actA);
    const unsigned balB = __ballot_sync(0xffffffffu, actB);
    if (lane == 0) {
        warpCnt[warp]     = __popc(balA);
        warpCnt[4 + warp] = __popc(balB);
    }
    __syncthreads();

    int M = 0;
    #pragma unroll
    for (int i = 0; i < 8; i++) M += warpCnt[i];

    int baseA = 0;
    for (int i = 0; i < warp; i++) baseA += warpCnt[i];
    int baseB = 0;
    for (int i = 0; i < 4 + warp; i++) baseB += warpCnt[i];

    const unsigned ltmask = (1u << lane) - 1u;
    if (actA) {
        const int pos = baseA + __popc(balA & ltmask);
        sC0[pos] = (int)truncf(l1a - 46.5f);
        #pragma unroll
        for (int r = 0; r < RPB; r++) {
            const int dr = da + r;
            sW[pos][r] = ((unsigned)dr < (unsigned)KS) ? gn[dr] : 0.0f;
        }
    }
    if (actB) {
        const int pos = baseB + __popc(balB & ltmask);
        sC0[pos] = (int)truncf(l1b - 46.5f);
        #pragma unroll
        for (int r = 0; r < RPB; r++) {
            const int dr = db + r;
            sW[pos][r] = ((unsigned)dr < (unsigned)KS) ? gn[dr] : 0.0f;
        }
    }
    __syncthreads();

    // ---- Phase 2: accumulate over the compact active list ----------------
    float acc[4][RPB];
    #pragma unroll
    for (int kk = 0; kk < 4; kk++)
        #pragma unroll
        for (int r = 0; r < RPB; r++) acc[kk][r] = 0.0f;

    for (int m = 0; m < M; m++) {
        const int c0 = sC0[m];
        const float4 w0 = *(const float4*)&sW[m][0];
        const float4 w1 = *(const float4*)&sW[m][4];
        const int d0 = t - c0;
        #pragma unroll
        for (int kk = 0; kk < 4; kk++) {
            const int d = d0 + kk * NT;
            if ((unsigned)d < (unsigned)KS) {
                const float gv = gn[d];           // conflict-free: d is lane-consecutive
                acc[kk][0] = fmaf(gv, w0.x, acc[kk][0]);
                acc[kk][1] = fmaf(gv, w0.y, acc[kk][1]);
                acc[kk][2] = fmaf(gv, w0.z, acc[kk][2]);
                acc[kk][3] = fmaf(gv, w0.w, acc[kk][3]);
                acc[kk][4] = fmaf(gv, w1.x, acc[kk][4]);
                acc[kk][5] = fmaf(gv, w1.y, acc[kk][5]);
                acc[kk][6] = fmaf(gv, w1.z, acc[kk][6]);
                acc[kk][7] = fmaf(gv, w1.w, acc[kk][7]);
            }
        }
    }

    // ---- Write 8 rows x 512 cols, fully coalesced ------------------------
    float* o = out + ((size_t)b * H_OUT + rowBase) * W_OUT;
    #pragma unroll
    for (int r = 0; r < RPB; r++)
        #pragma unroll
        for (int kk = 0; kk < 4; kk++)
            o[r * W_OUT + kk * NT + t] = acc[kk][r];
}

extern "C" void kernel_launch(void* const* d_in, const int* in_sizes, int n_in,
                              void* d_out, int out_size) {
    // metadata order: [0] batch_images (unused by the math),
    //                 [1] batch_labels [8,256,2] f32, [2] sigma scalar f32
    const float* labels = (const float*)d_in[1];
    const float* sigma  = (const float*)d_in[2];
    float* out = (float*)d_out;                   // [8,1,512,512] f32

    gauss_setup_kernel<<<1, 128>>>(sigma);
    density_kernel<<<8 * (H_OUT / RPB), NT>>>(labels, out);
}

// round 4
// speedup vs baseline: 3.4909x; 1.2286x over previous
#include <cuda_runtime.h>

#define KS 93          // gaussian kernel size (static, matches reference)
#define NPTS 256       // points per batch
#define W_OUT 512
#define H_OUT 512
#define RPB 8          // rows per block
#define SLABW 128      // columns per block (one per thread)
#define NT 128         // threads per block
#define PAD 127        // left zero-padding of the gaussian table
#define GNP_LEN (PAD + 220)  // covers index t + dd, dd in [0, 219]; zeros outside weights

// One block per (batch, 8-row group, 128-col slab).  grid = 8*64*4 = 2048.
// Thread t owns column colBase+t for 8 rows (8 accumulators).
// The gaussian table is built in-block (fused setup: no second kernel).
__global__ __launch_bounds__(NT)
void density_kernel(const float* __restrict__ labels,
                    const float* __restrict__ sigma_ptr,
                    float* __restrict__ out) {
    const int slab    = blockIdx.x & 3;
    const int rowBase = ((blockIdx.x >> 2) & 63) * RPB;
    const int b       = blockIdx.x >> 8;
    const int colBase = slab * SLABW;
    const int t    = threadIdx.x;
    const int warp = t >> 5;
    const int lane = t & 31;

    __shared__ __align__(16) float sW[NPTS][RPB]; // 8 row-weights per active point
    __shared__ float gnp[GNP_LEN];                // zero-padded normalized gaussian
    __shared__ int   sD[NPTS];                    // PAD + colBase - c0 per active point
    __shared__ float wsum[4];
    __shared__ int   warpCnt[8];                  // 4 warps x 2 passes

    // ---- Fused gaussian setup (per block; deterministic) -----------------
    const float s = fabsf(sigma_ptr[0]);
    const float inv2s2 = 1.0f / (2.0f * s * s);
    float gval = 0.0f;
    if (t < KS) {
        const float a = (float)(t - KS / 2);      // [-46, 46]
        gval = expf(-(a * a) * inv2s2);
    }
    // block-wide sum of gval (order fixed -> deterministic)
    float v = gval;
    #pragma unroll
    for (int off = 16; off > 0; off >>= 1) v += __shfl_down_sync(0xffffffffu, v, off);
    if (lane == 0) wsum[warp] = v;
    // zero-fill the padded table
    #pragma unroll
    for (int i = t; i < GNP_LEN; i += NT) gnp[i] = 0.0f;
    __syncthreads();
    const float total = wsum[0] + wsum[1] + wsum[2] + wsum[3];
    if (t < KS) gnp[PAD + t] = gval / total;
    __syncthreads();

    // ---- Phase 1: classify all 256 points, ballot-compact ----------------
    const float* lab = labels + (size_t)b * NPTS * 2;
    const float l0a = lab[2 * t + 0];
    const float l1a = lab[2 * t + 1];
    const float l0b = lab[2 * (t + NT) + 0];
    const float l1b = lab[2 * (t + NT) + 1];
    // row window: da = rowBase - trunc(l0 - 46.5); active iff da in [-7, 92]
    const int da = rowBase - (int)truncf(l0a - 46.5f);
    const int db = rowBase - (int)truncf(l0b - 46.5f);
    // col window: dc = colBase - trunc(l1 - 46.5); slab hit iff dc in [-127, 92]
    const int dca = colBase - (int)truncf(l1a - 46.5f);
    const int dcb = colBase - (int)truncf(l1b - 46.5f);
    const bool actA = ((unsigned)(da + RPB - 1) < (unsigned)(KS + RPB - 1)) &&
                      ((unsigned)(dca + PAD)    < (unsigned)(KS + PAD));
    const bool actB = ((unsigned)(db + RPB - 1) < (unsigned)(KS + RPB - 1)) &&
                      ((unsigned)(dcb + PAD)    < (unsigned)(KS + PAD));
    const unsigned balA = __ballot_sync(0xffffffffu, actA);
    const unsigned balB = __ballot_sync(0xffffffffu, actB);
    if (lane == 0) {
        warpCnt[warp]     = __popc(balA);
        warpCnt[4 + warp] = __popc(balB);
    }
    __syncthreads();

    int M = 0;
    #pragma unroll
    for (int i = 0; i < 8; i++) M += warpCnt[i];
    int baseA = 0;
    for (int i = 0; i < warp; i++) baseA += warpCnt[i];
    int baseB = 0;
    for (int i = 0; i < 4 + warp; i++) baseB += warpCnt[i];

    const unsigned ltmask = (1u << lane) - 1u;
    if (actA) {
        const int pos = baseA + __popc(balA & ltmask);
        sD[pos] = PAD + dca;
        #pragma unroll
        for (int r = 0; r < RPB; r++)             // zeros come free from padding
            sW[pos][r] = gnp[PAD + da + r];
    }
    if (actB) {
        const int pos = baseB + __popc(balB & ltmask);
        sD[pos] = PAD + dcb;
        #pragma unroll
        for (int r = 0; r < RPB; r++)
            sW[pos][r] = gnp[PAD + db + r];
    }
    __syncthreads();

    // ---- Phase 2: accumulate over the compact list (~21 points) ----------
    float acc[RPB];
    #pragma unroll
    for (int r = 0; r < RPB; r++) acc[r] = 0.0f;

    #pragma unroll 4
    for (int m = 0; m < M; m++) {
        const int dd = sD[m];                     // broadcast LDS
        const float4 w0 = *(const float4*)&sW[m][0];
        const float4 w1 = *(const float4*)&sW[m][4];
        const float gv = gnp[t + dd];             // conflict-free, zero-padded
        acc[0] = fmaf(gv, w0.x, acc[0]);
        acc[1] = fmaf(gv, w0.y, acc[1]);
        acc[2] = fmaf(gv, w0.z, acc[2]);
        acc[3] = fmaf(gv, w0.w, acc[3]);
        acc[4] = fmaf(gv, w1.x, acc[4]);
        acc[5] = fmaf(gv, w1.y, acc[5]);
        acc[6] = fmaf(gv, w1.z, acc[6]);
        acc[7] = fmaf(gv, w1.w, acc[7]);
    }

    // ---- Write 8 rows x 128 cols, coalesced ------------------------------
    float* o = out + ((size_t)b * H_OUT + rowBase) * W_OUT + colBase;
    #pragma unroll
    for (int r = 0; r < RPB; r++)
        o[r * W_OUT + t] = acc[r];
}

extern "C" void kernel_launch(void* const* d_in, const int* in_sizes, int n_in,
                              void* d_out, int out_size) {
    // metadata order: [0] batch_images (unused by the math),
    //                 [1] batch_labels [8,256,2] f32, [2] sigma scalar f32
    const float* labels = (const float*)d_in[1];
    const float* sigma  = (const float*)d_in[2];
    float* out = (float*)d_out;                   // [8,1,512,512] f32

    density_kernel<<<8 * (H_OUT / RPB) * (W_OUT / SLABW), NT>>>(labels, sigma, out);
}

// round 5
// speedup vs baseline: 3.5368x; 1.0132x over previous
#include <cuda_runtime.h>
#include <cstdint>

#define KS 93          // gaussian kernel size (static, matches reference)
#define NPTS 256       // points per batch
#define W_OUT 512
#define H_OUT 512
#define RPB 16         // rows per block (8 packed f32x2 accumulators)
#define SLABW 128      // columns per block (one per thread)
#define NT 128         // threads per block
#define PAD 127        // left zero-padding of the gaussian table
#define GNP_LEN (PAD + 220)  // zeros outside [PAD, PAD+93)

// One block per (batch, 16-row group, 128-col slab).  grid = 8*32*4 = 1024.
// Thread t owns column colBase+t for 16 rows, accumulated as 8 f32x2 pairs.
__global__ __launch_bounds__(NT)
void density_kernel(const float* __restrict__ labels,
                    const float* __restrict__ sigma_ptr,
                    float* __restrict__ out) {
    const int slab    = blockIdx.x & 3;
    const int rowBase = ((blockIdx.x >> 2) & 31) * RPB;
    const int b       = blockIdx.x >> 7;
    const int colBase = slab * SLABW;
    const int t    = threadIdx.x;
    const int warp = t >> 5;
    const int lane = t & 31;

    __shared__ __align__(16) float sW[NPTS][RPB]; // 16 row-weights per active point
    __shared__ float gnp[GNP_LEN];                // zero-padded normalized gaussian
    __shared__ int   sD[NPTS];                    // PAD + colBase - C0 per active point
    __shared__ float wsum[4];
    __shared__ int   warpCnt[8];                  // 4 warps x 2 passes

    // ---- Fused gaussian setup (per block; deterministic) -----------------
    const float s = fabsf(sigma_ptr[0]);
    const float inv2s2 = 1.0f / (2.0f * s * s);
    float gval = 0.0f;
    if (t < KS) {
        const float a = (float)(t - KS / 2);      // [-46, 46]
        gval = expf(-(a * a) * inv2s2);
    }
    float v = gval;
    #pragma unroll
    for (int off = 16; off > 0; off >>= 1) v += __shfl_down_sync(0xffffffffu, v, off);
    if (lane == 0) wsum[warp] = v;
    #pragma unroll
    for (int i = t; i < GNP_LEN; i += NT) gnp[i] = 0.0f;
    __syncthreads();
    const float total = wsum[0] + wsum[1] + wsum[2] + wsum[3];
    if (t < KS) gnp[PAD + t] = gval / total;
    __syncthreads();

    // ---- Phase 1: classify all 256 points, ballot-compact ----------------
    const float2* lab = (const float2*)(labels + (size_t)b * NPTS * 2);
    const float2 pa = lab[t];                     // (row-coord, col-coord)
    const float2 pb = lab[t + NT];
    // row window: da = rowBase - trunc(l0 - 46.5); active iff da in [-15, 92]
    const int da = rowBase - (int)truncf(pa.x - 46.5f);
    const int db = rowBase - (int)truncf(pb.x - 46.5f);
    // col window: dc = colBase - trunc(l1 - 46.5); slab hit iff dc in [-127, 92]
    const int dca = colBase - (int)truncf(pa.y - 46.5f);
    const int dcb = colBase - (int)truncf(pb.y - 46.5f);
    const bool actA = ((unsigned)(da + RPB - 1) < (unsigned)(KS + RPB - 1)) &&
                      ((unsigned)(dca + PAD)    < (unsigned)(KS + PAD));
    const bool actB = ((unsigned)(db + RPB - 1) < (unsigned)(KS + RPB - 1)) &&
                      ((unsigned)(dcb + PAD)    < (unsigned)(KS + PAD));
    const unsigned balA = __ballot_sync(0xffffffffu, actA);
    const unsigned balB = __ballot_sync(0xffffffffu, actB);
    if (lane == 0) {
        warpCnt[warp]     = __popc(balA);
        warpCnt[4 + warp] = __popc(balB);
    }
    __syncthreads();

    int M = 0;
    #pragma unroll
    for (int i = 0; i < 8; i++) M += warpCnt[i];
    int baseA = 0;
    for (int i = 0; i < warp; i++) baseA += warpCnt[i];
    int baseB = 0;
    for (int i = 0; i < 4 + warp; i++) baseB += warpCnt[i];

    const unsigned ltmask = (1u << lane) - 1u;
    if (actA) {
        const int pos = baseA + __popc(balA & ltmask);
        sD[pos] = PAD + dca;
        #pragma unroll
        for (int r = 0; r < RPB; r++)             // zeros come free from padding
            sW[pos][r] = gnp[PAD + da + r];
    }
    if (actB) {
        const int pos = baseB + __popc(balB & ltmask);
        sD[pos] = PAD + dcb;
        #pragma unroll
        for (int r = 0; r < RPB; r++)
            sW[pos][r] = gnp[PAD + db + r];
    }
    __syncthreads();

    // ---- Phase 2: packed f32x2 accumulation over compact list (~23 pts) --
    uint64_t acc[RPB / 2];
    #pragma unroll
    for (int i = 0; i < RPB / 2; i++) acc[i] = 0ull;

    #pragma unroll 2
    for (int m = 0; m < M; m++) {
        const int dd = sD[m];                       // broadcast LDS
        const ulonglong2* wp = (const ulonglong2*)&sW[m][0];
        const ulonglong2 p0 = wp[0];                // rows 0-3  (2 packed pairs)
        const ulonglong2 p1 = wp[1];                // rows 4-7
        const ulonglong2 p2 = wp[2];                // rows 8-11
        const ulonglong2 p3 = wp[3];                // rows 12-15
        const float gv = gnp[t + dd];               // conflict-free, zero-padded
        const uint32_t gvu = __float_as_uint(gv);
        uint64_t gv2;
        asm("mov.b64 %0, {%1, %1};" : "=l"(gv2) : "r"(gvu));
        asm("fma.rn.f32x2 %0, %1, %2, %0;" : "+l"(acc[0]) : "l"(gv2), "l"(p0.x));
        asm("fma.rn.f32x2 %0, %1, %2, %0;" : "+l"(acc[1]) : "l"(gv2), "l"(p0.y));
        asm("fma.rn.f32x2 %0, %1, %2, %0;" : "+l"(acc[2]) : "l"(gv2), "l"(p1.x));
        asm("fma.rn.f32x2 %0, %1, %2, %0;" : "+l"(acc[3]) : "l"(gv2), "l"(p1.y));
        asm("fma.rn.f32x2 %0, %1, %2, %0;" : "+l"(acc[4]) : "l"(gv2), "l"(p2.x));
        asm("fma.rn.f32x2 %0, %1, %2, %0;" : "+l"(acc[5]) : "l"(gv2), "l"(p2.y));
        asm("fma.rn.f32x2 %0, %1, %2, %0;" : "+l"(acc[6]) : "l"(gv2), "l"(p3.x));
        asm("fma.rn.f32x2 %0, %1, %2, %0;" : "+l"(acc[7]) : "l"(gv2), "l"(p3.y));
    }

    // ---- Write 16 rows x 128 cols, coalesced -----------------------------
    float* o = out + ((size_t)b * H_OUT + rowBase) * W_OUT + colBase;
    #pragma unroll
    for (int i = 0; i < RPB / 2; i++) {
        uint32_t lo, hi;
        asm("mov.b64 {%0, %1}, %2;" : "=r"(lo), "=r"(hi) : "l"(acc[i]));
        o[(2 * i + 0) * W_OUT + t] = __uint_as_float(lo);
        o[(2 * i + 1) * W_OUT + t] = __uint_as_float(hi);
    }
}

extern "C" void kernel_launch(void* const* d_in, const int* in_sizes, int n_in,
                              void* d_out, int out_size) {
    // metadata order: [0] batch_images (unused by the math),
    //                 [1] batch_labels [8,256,2] f32, [2] sigma scalar f32
    const float* labels = (const float*)d_in[1];
    const float* sigma  = (const float*)d_in[2];
    float* out = (float*)d_out;                   // [8,1,512,512] f32

    density_kernel<<<8 * (H_OUT / RPB) * (W_OUT / SLABW), NT>>>(labels, sigma, out);
}